// round 5
// baseline (speedup 1.0000x reference)
#include <cuda_runtime.h>
#include <math.h>

#define BB 4
#define BEAMW 5
#define NSEQ 20
#define TMAXX 16
#define BUFL 17
#define VV 50257
#define DD 768
#define HH 12
#define DHH 64
#define NLL 2
#define SSL 128
#define DFFL 3072
#define TOK_SOS 1
#define TOK_EOS 2
#define NEGINF (-1e20f)

// persistent scratch (no allocs allowed)
__device__ float g_x[NSEQ][DD];
__device__ float g_y[NSEQ][DD];
__device__ float g_attn[NSEQ][DD];
__device__ float g_t1[NSEQ * DFFL];
__device__ float g_logits[NSEQ][VV];
__device__ float g_mx[NSEQ];
__device__ float g_lse[NSEQ];
__device__ float g_cacheK[2][NLL][NSEQ][BUFL][DD];
__device__ float g_cacheV[2][NLL][NSEQ][BUFL][DD];
__device__ float g_crossKV[NLL][BB * SSL][2 * DD];
__device__ int   g_buf[BB][BEAMW][BUFL];
__device__ float g_scores[BB][BEAMW];
__device__ int   g_prevK[BB][BEAMW];

// ---- GEMM: out[N][M] = epi(X[N][K] @ W[M][K]^T + bias) (+ resid). K % 128 == 0. ----
#define KST 128
#define NT 20
__global__ __launch_bounds__(128) void gemm_kernel(
    const float* __restrict__ X, const float* __restrict__ W,
    const float* __restrict__ bias, const float* __restrict__ resid,
    float* __restrict__ out, int Nrows, int M, int K, int epi)
{
    __shared__ float4 xs4[NT][KST / 4];
    __shared__ float  ws[KST][33];
    __shared__ float  red[4][NT][32];
    const int tid = threadIdx.x, lane = tid & 31, warp = tid >> 5;
    const int m0 = blockIdx.x * 32, n0 = blockIdx.y * NT;

    float acc[NT];
#pragma unroll
    for (int i = 0; i < NT; i++) acc[i] = 0.f;

    for (int k0 = 0; k0 < K; k0 += KST) {
        for (int f = tid; f < NT * (KST / 4); f += 128) {
            int r = f >> 5, kq = f & 31;
            float4 v = make_float4(0.f, 0.f, 0.f, 0.f);
            if (n0 + r < Nrows)
                v = *(const float4*)(X + (size_t)(n0 + r) * K + k0 + kq * 4);
            xs4[r][kq] = v;
        }
        for (int f = tid; f < 32 * (KST / 4); f += 128) {
            int m = f >> 5, kq = f & 31;
            float4 v = make_float4(0.f, 0.f, 0.f, 0.f);
            if (m0 + m < M)
                v = *(const float4*)(W + (size_t)(m0 + m) * K + k0 + kq * 4);
            ws[kq * 4 + 0][m] = v.x; ws[kq * 4 + 1][m] = v.y;
            ws[kq * 4 + 2][m] = v.z; ws[kq * 4 + 3][m] = v.w;
        }
        __syncthreads();
#pragma unroll
        for (int kq = 0; kq < 8; kq++) {
            int kk = (warp * 8 + kq) * 4;
            float w0 = ws[kk + 0][lane], w1 = ws[kk + 1][lane];
            float w2 = ws[kk + 2][lane], w3 = ws[kk + 3][lane];
#pragma unroll
            for (int n = 0; n < NT; n++) {
                float4 xv = xs4[n][kk >> 2];
                acc[n] += xv.x * w0 + xv.y * w1 + xv.z * w2 + xv.w * w3;
            }
        }
        __syncthreads();
    }
#pragma unroll
    for (int n = 0; n < NT; n++) red[warp][n][lane] = acc[n];
    __syncthreads();
    int m = m0 + lane;
    if (m < M) {
        float bv = bias ? bias[m] : 0.f;
        for (int q = 0; q < 5; q++) {
            int n = warp * 5 + q;
            if (n0 + n >= Nrows) break;
            float s = red[0][n][lane] + red[1][n][lane] + red[2][n][lane] + red[3][n][lane] + bv;
            if (epi == 1) s = fmaxf(s, 0.f);
            else if (epi == 2) s = tanhf(s);
            if (resid) s += resid[(size_t)(n0 + n) * M + m];
            out[(size_t)(n0 + n) * M + m] = s;
        }
    }
}

// ---- reductions ----
__device__ __forceinline__ float blk_sum(float v, float* sh) {
    int lane = threadIdx.x & 31, w = threadIdx.x >> 5, nw = blockDim.x >> 5;
#pragma unroll
    for (int o = 16; o; o >>= 1) v += __shfl_xor_sync(0xffffffffu, v, o);
    if (lane == 0) sh[w] = v;
    __syncthreads();
    if (w == 0) {
        float r = (lane < nw) ? sh[lane] : 0.f;
#pragma unroll
        for (int o = 16; o; o >>= 1) r += __shfl_xor_sync(0xffffffffu, r, o);
        if (lane == 0) sh[0] = r;
    }
    __syncthreads();
    float r = sh[0];
    __syncthreads();
    return r;
}
__device__ __forceinline__ float blk_max(float v, float* sh) {
    int lane = threadIdx.x & 31, w = threadIdx.x >> 5, nw = blockDim.x >> 5;
#pragma unroll
    for (int o = 16; o; o >>= 1) v = fmaxf(v, __shfl_xor_sync(0xffffffffu, v, o));
    if (lane == 0) sh[w] = v;
    __syncthreads();
    if (w == 0) {
        float r = (lane < nw) ? sh[lane] : -INFINITY;
#pragma unroll
        for (int o = 16; o; o >>= 1) r = fmaxf(r, __shfl_xor_sync(0xffffffffu, r, o));
        if (lane == 0) sh[0] = r;
    }
    __syncthreads();
    float r = sh[0];
    __syncthreads();
    return r;
}

__device__ void ln_row(const float* in, const float* gg, const float* bb2, float* out, float* sh) {
    float ls = 0.f;
    for (int d = threadIdx.x; d < DD; d += blockDim.x) ls += in[d];
    float mean = blk_sum(ls, sh) * (1.0f / DD);
    float lv = 0.f;
    for (int d = threadIdx.x; d < DD; d += blockDim.x) { float t = in[d] - mean; lv += t * t; }
    float var = blk_sum(lv, sh) * (1.0f / DD);
    float rstd = rsqrtf(var + 1e-5f);
    for (int d = threadIdx.x; d < DD; d += blockDim.x)
        out[d] = (in[d] - mean) * rstd * gg[d] + bb2[d];
}

__global__ void ln_kernel(const float* in, const float* gg, const float* bb2, float* out) {
    __shared__ float sh[8];
    int n = blockIdx.x;
    ln_row(in + (size_t)n * DD, gg, bb2, out + (size_t)n * DD, sh);
}

__global__ void embed_ln_kernel(const float* __restrict__ emb, const float* __restrict__ pos,
                                const float* gg, const float* bb2, int t) {
    __shared__ float xr[DD];
    __shared__ float sh[8];
    int n = blockIdx.x;
    int tok = g_buf[n / BEAMW][n % BEAMW][t];
    for (int d = threadIdx.x; d < DD; d += blockDim.x)
        xr[d] = emb[(size_t)tok * DD + d] + pos[(size_t)t * DD + d];
    __syncthreads();
    ln_row(xr, gg, bb2, &g_x[n][0], sh);
}

__global__ void copykv_kernel(int l, int t, int pp) {
    int n = blockIdx.x;
    for (int d = threadIdx.x; d < DD; d += blockDim.x) {
        g_cacheK[pp][l][n][t][d] = g_t1[n * (3 * DD) + DD + d];
        g_cacheV[pp][l][n][t][d] = g_t1[n * (3 * DD) + 2 * DD + d];
    }
}

__global__ void selfattn_kernel(int l, int t, int pp) {
    int n = blockIdx.x, h = blockIdx.y, lane = threadIdx.x;
    __shared__ float a[BUFL];
    const float* q = g_t1 + n * (3 * DD) + h * DHH;
    float s = -INFINITY;
    if (lane <= t) {
        const float* Kr = &g_cacheK[pp][l][n][lane][h * DHH];
        float d = 0.f;
#pragma unroll
        for (int i = 0; i < DHH; i++) d += q[i] * Kr[i];
        s = d * 0.125f;
    }
    float mx = s;
#pragma unroll
    for (int o = 16; o; o >>= 1) mx = fmaxf(mx, __shfl_xor_sync(0xffffffffu, mx, o));
    float e = (lane <= t) ? expf(s - mx) : 0.f;
    float sum = e;
#pragma unroll
    for (int o = 16; o; o >>= 1) sum += __shfl_xor_sync(0xffffffffu, sum, o);
    if (lane <= t) a[lane] = e / sum;
    __syncwarp();
    float o0 = 0.f, o1 = 0.f;
    for (int j = 0; j <= t; j++) {
        const float* Vr = &g_cacheV[pp][l][n][j][h * DHH];
        float p = a[j];
        o0 += p * Vr[lane];
        o1 += p * Vr[lane + 32];
    }
    g_attn[n][h * DHH + lane] = o0;
    g_attn[n][h * DHH + lane + 32] = o1;
}

__global__ __launch_bounds__(128) void crossattn_kernel(int l, const int* __restrict__ source_mask) {
    int n = blockIdx.x, h = blockIdx.y, b = n / BEAMW, j = threadIdx.x;
    __shared__ float red[SSL];
    __shared__ float a[SSL];
    const float* q = g_t1 + n * DD + h * DHH;
    const float* Kr = &g_crossKV[l][b * SSL + j][h * DHH];
    float d = 0.f;
#pragma unroll
    for (int i = 0; i < DHH; i++) d += q[i] * Kr[i];
    float s = d * 0.125f;
    if (source_mask[b * SSL + j] == 0) s = -1e9f;
    red[j] = s; __syncthreads();
    for (int st = 64; st >= 1; st >>= 1) { if (j < st) red[j] = fmaxf(red[j], red[j + st]); __syncthreads(); }
    float mx = red[0]; __syncthreads();
    float p = expf(s - mx);
    red[j] = p; __syncthreads();
    for (int st = 64; st >= 1; st >>= 1) { if (j < st) red[j] += red[j + st]; __syncthreads(); }
    float sum = red[0]; __syncthreads();
    a[j] = p / sum; __syncthreads();
    if (j < DHH) {
        float o = 0.f;
        for (int k = 0; k < SSL; k++)
            o += a[k] * g_crossKV[l][b * SSL + k][DD + h * DHH + j];
        g_attn[n][h * DHH + j] = o;
    }
}

__global__ void lse_kernel() {
    __shared__ float sh[8];
    int n = blockIdx.x;
    const float* row = &g_logits[n][0];
    float lm = -INFINITY;
    for (int i = threadIdx.x; i < VV; i += blockDim.x) lm = fmaxf(lm, row[i]);
    float mx = blk_max(lm, sh);
    float ls = 0.f;
    for (int i = threadIdx.x; i < VV; i += blockDim.x) ls += expf(row[i] - mx);
    float s = blk_sum(ls, sh);
    if (threadIdx.x == 0) { g_mx[n] = mx; g_lse[n] = logf(s); }
}

// exact jax.lax.top_k semantics: value desc, ties -> smaller index
__global__ __launch_bounds__(256) void topk_kernel(int t) {
    __shared__ int   s_oldbuf[BEAMW * BUFL];
    __shared__ float s_sc[BEAMW];
    __shared__ int   s_eos[BEAMW];
    __shared__ float mv[256][5];
    __shared__ int   mi[256][5];
    int b = blockIdx.x, tid = threadIdx.x;
    if (tid < BEAMW * BUFL) s_oldbuf[tid] = g_buf[b][tid / BUFL][tid % BUFL];
    if (tid < BEAMW) { s_sc[tid] = g_scores[b][tid]; s_eos[tid] = (g_buf[b][tid][t] == TOK_EOS) ? 1 : 0; }
    __syncthreads();
    float tv[5]; int ti[5];
#pragma unroll
    for (int q = 0; q < 5; q++) { tv[q] = -INFINITY; ti[q] = 0x7fffffff; }
    for (int i = tid; i < BEAMW * VV; i += 256) {
        int j = i / VV, v = i - j * VV;
        float val;
        if (s_eos[j]) val = NEGINF;
        else {
            int nn = b * BEAMW + j;
            val = s_sc[j] + (g_logits[nn][v] - g_mx[nn] - g_lse[nn]);
        }
        if (val > tv[4] || (val == tv[4] && i < ti[4])) {
            int p = 4;
            while (p > 0 && (val > tv[p - 1] || (val == tv[p - 1] && i < ti[p - 1]))) {
                tv[p] = tv[p - 1]; ti[p] = ti[p - 1]; p--;
            }
            tv[p] = val; ti[p] = i;
        }
    }
#pragma unroll
    for (int q = 0; q < 5; q++) { mv[tid][q] = tv[q]; mi[tid][q] = ti[q]; }
    __syncthreads();
    for (int stride = 128; stride >= 1; stride >>= 1) {
        if (tid < stride) {
            float av[5], bv5[5]; int ai[5], bi5[5];
#pragma unroll
            for (int q = 0; q < 5; q++) {
                av[q] = mv[tid][q]; ai[q] = mi[tid][q];
                bv5[q] = mv[tid + stride][q]; bi5[q] = mi[tid + stride][q];
            }
            int ia = 0, ib = 0;
            float rv[5]; int ri[5];
#pragma unroll
            for (int q = 0; q < 5; q++) {
                bool ta = (av[ia] > bv5[ib]) || (av[ia] == bv5[ib] && ai[ia] < bi5[ib]);
                if (ta) { rv[q] = av[ia]; ri[q] = ai[ia]; ia++; }
                else    { rv[q] = bv5[ib]; ri[q] = bi5[ib]; ib++; }
            }
#pragma unroll
            for (int q = 0; q < 5; q++) { mv[tid][q] = rv[q]; mi[tid][q] = ri[q]; }
        }
        __syncthreads();
    }
    if (tid < BEAMW) {
        int id = mi[0][tid];
        int pk = id / VV;
        int tok = id - pk * VV;
        g_scores[b][tid] = mv[0][tid];
        g_prevK[b][tid] = pk;
        for (int p = 0; p < BUFL; p++)
            g_buf[b][tid][p] = (p == t + 1) ? tok : s_oldbuf[pk * BUFL + p];
    }
}

__global__ void gather_kernel(int pp) {
    int j = blockIdx.x, n = blockIdx.y, z = blockIdx.z;
    int l = z >> 1, kv = z & 1;
    int b = n / BEAMW, k = n % BEAMW;
    int src = b * BEAMW + g_prevK[b][k];
    const float* s; float* dpt;
    if (kv == 0) { s = &g_cacheK[pp][l][src][j][0]; dpt = &g_cacheK[1 - pp][l][n][j][0]; }
    else         { s = &g_cacheV[pp][l][src][j][0]; dpt = &g_cacheV[1 - pp][l][n][j][0]; }
    for (int i = threadIdx.x; i < DD; i += blockDim.x) dpt[i] = s[i];
}

__global__ void init_kernel() {
    int tid = threadIdx.x;
    if (tid < BB * BEAMW * BUFL) {
        int b = tid / (BEAMW * BUFL), r = tid % (BEAMW * BUFL);
        int k = r / BUFL, p = r % BUFL;
        g_buf[b][k][p] = (k == 0 && p == 0) ? TOK_SOS : 0;
    }
    if (tid < BB * BEAMW)
        ((float*)g_scores)[tid] = (tid % BEAMW == 0) ? 0.f : NEGINF;
}

__global__ void writeout_kernel(float* out) {
    int tid = threadIdx.x;
    if (tid < BB * BEAMW) {
        int b = tid / BEAMW, k = tid % BEAMW;
        out[tid] = g_scores[b][k];
        int cum = 0;
        for (int i = 1; i <= TMAXX; i++) {
            int tok = g_buf[b][k][i];
            if (tok == TOK_EOS) cum++;
            out[BB * BEAMW + tid * TMAXX + (i - 1)] = (cum == 0) ? (float)tok : 0.f;
        }
    }
}

extern "C" void kernel_launch(void* const* d_in, const int* in_sizes, int n_in,
                              void* d_out, int out_size) {
    (void)in_sizes; (void)n_in; (void)out_size;
    const float* emb         = (const float*)d_in[0];
    const float* pos         = (const float*)d_in[1];
    const float* ln_emb_g    = (const float*)d_in[2];
    const float* ln_emb_b    = (const float*)d_in[3];
    const float* self_in_w   = (const float*)d_in[4];
    const float* self_in_b   = (const float*)d_in[5];
    const float* self_out_w  = (const float*)d_in[6];
    const float* self_out_b  = (const float*)d_in[7];
    const float* cross_in_w  = (const float*)d_in[8];
    const float* cross_in_b  = (const float*)d_in[9];
    const float* cross_out_w = (const float*)d_in[10];
    const float* cross_out_b = (const float*)d_in[11];
    const float* ff1_w       = (const float*)d_in[12];
    const float* ff1_b       = (const float*)d_in[13];
    const float* ff2_w       = (const float*)d_in[14];
    const float* ff2_b       = (const float*)d_in[15];
    const float* ln1_g       = (const float*)d_in[16];
    const float* ln1_b       = (const float*)d_in[17];
    const float* ln2_g       = (const float*)d_in[18];
    const float* ln2_b       = (const float*)d_in[19];
    const float* ln3_g       = (const float*)d_in[20];
    const float* ln3_b       = (const float*)d_in[21];
    const float* dense_w     = (const float*)d_in[22];
    const float* dense_b     = (const float*)d_in[23];
    const float* context     = (const float*)d_in[24];
    const int*   source_mask = (const int*)d_in[25];

    void* tmp;
    float *pt1, *pattn, *px, *py, *plog, *pcross;
    cudaGetSymbolAddress(&tmp, g_t1);      pt1    = (float*)tmp;
    cudaGetSymbolAddress(&tmp, g_attn);    pattn  = (float*)tmp;
    cudaGetSymbolAddress(&tmp, g_x);       px     = (float*)tmp;
    cudaGetSymbolAddress(&tmp, g_y);       py     = (float*)tmp;
    cudaGetSymbolAddress(&tmp, g_logits);  plog   = (float*)tmp;
    cudaGetSymbolAddress(&tmp, g_crossKV); pcross = (float*)tmp;

    init_kernel<<<1, 512>>>();

    // cross-attn K|V precompute: rows D..3D of cross_in_w are contiguous -> one GEMM, M=2*DD
    for (int l = 0; l < NLL; l++) {
        gemm_kernel<<<dim3((2 * DD) / 32, (BB * SSL + NT - 1) / NT), 128>>>(
            context,
            cross_in_w + (size_t)l * 3 * DD * DD + (size_t)DD * DD,
            cross_in_b + (size_t)l * 3 * DD + DD,
            nullptr,
            pcross + (size_t)l * BB * SSL * 2 * DD,
            BB * SSL, 2 * DD, DD, 0);
    }

    int pp = 0;
    for (int t = 0; t < TMAXX; t++) {
        embed_ln_kernel<<<NSEQ, 256>>>(emb, pos, ln_emb_g, ln_emb_b, t);
        for (int l = 0; l < NLL; l++) {
            gemm_kernel<<<dim3(72, 1), 128>>>(px, self_in_w + (size_t)l * 3 * DD * DD,
                self_in_b + (size_t)l * 3 * DD, nullptr, pt1, NSEQ, 3 * DD, DD, 0);
            copykv_kernel<<<NSEQ, 256>>>(l, t, pp);
            selfattn_kernel<<<dim3(NSEQ, HH), 32>>>(l, t, pp);
            gemm_kernel<<<dim3(24, 1), 128>>>(pattn, self_out_w + (size_t)l * DD * DD,
                self_out_b + (size_t)l * DD, px, py, NSEQ, DD, DD, 0);
            ln_kernel<<<NSEQ, 256>>>(py, ln1_g + (size_t)l * DD, ln1_b + (size_t)l * DD, px);

            gemm_kernel<<<dim3(24, 1), 128>>>(px, cross_in_w + (size_t)l * 3 * DD * DD,
                cross_in_b + (size_t)l * 3 * DD, nullptr, pt1, NSEQ, DD, DD, 0);
            crossattn_kernel<<<dim3(NSEQ, HH), 128>>>(l, source_mask);
            gemm_kernel<<<dim3(24, 1), 128>>>(pattn, cross_out_w + (size_t)l * DD * DD,
                cross_out_b + (size_t)l * DD, px, py, NSEQ, DD, DD, 0);
            ln_kernel<<<NSEQ, 256>>>(py, ln2_g + (size_t)l * DD, ln2_b + (size_t)l * DD, px);

            gemm_kernel<<<dim3(96, 1), 128>>>(px, ff1_w + (size_t)l * DFFL * DD,
                ff1_b + (size_t)l * DFFL, nullptr, pt1, NSEQ, DFFL, DD, 1);
            gemm_kernel<<<dim3(24, 1), 128>>>(pt1, ff2_w + (size_t)l * DD * DFFL,
                ff2_b + (size_t)l * DD, px, py, NSEQ, DD, DFFL, 0);
            ln_kernel<<<NSEQ, 256>>>(py, ln3_g + (size_t)l * DD, ln3_b + (size_t)l * DD, px);
        }
        gemm_kernel<<<dim3(24, 1), 128>>>(px, dense_w, dense_b, nullptr, py, NSEQ, DD, DD, 2);
        gemm_kernel<<<dim3((VV + 31) / 32, 1), 128>>>(py, emb, nullptr, nullptr, plog, NSEQ, VV, DD, 0);
        lse_kernel<<<NSEQ, 256>>>();
        topk_kernel<<<BB, 256>>>(t);
        gather_kernel<<<dim3(BUFL, NSEQ, NLL * 2), 192>>>(pp);
        pp ^= 1;
    }
    writeout_kernel<<<1, 64>>>((float*)d_out);
}